// round 7
// baseline (speedup 1.0000x reference)
#include <cuda_runtime.h>

// FullPairwise (non-PBC): output layout (float32), MP = M*P:
//   [0      , 2*MP) : atom_index12   out[r*MP + m*P + p] = (r? j : i) + m*N
//   [2*MP   , 5*MP) : shift_values   zeros (flat region, filled coalesced)
//   [5*MP   , 6*MP) : mask           1.0f if d2 <= 5.2^2 else 0.0f
// Total = 6*MP floats = 201 MB -> all offsets fit in uint32.
static constexpr int      NA = 2048;
static constexpr int      NM = 4;
static constexpr unsigned PP = (unsigned)NA * (NA - 1) / 2;   // 2,096,128 (div by 256)
static constexpr unsigned MP = (unsigned)NM * PP;             // 8,384,512

static constexpr int      THREADS      = 256;
static constexpr unsigned PAIR_T       = PP / 8;                                  // 262,016
static constexpr int      PAIR_BLOCKS  = (int)((PAIR_T + THREADS - 1) / THREADS); // 1024
static constexpr unsigned ZERO_F4      = 3 * MP / 4;                              // 6,288,384
static constexpr int      ZERO_BLOCKS  = (int)((ZERO_F4 + THREADS - 1) / THREADS);// 24,564

// SoA coordinate scratch: [c][m*NA + a], c = 0/1/2 -> x/y/z.  98,304 bytes.
__device__ float g_soa[3][NM * NA];

__global__ void __launch_bounds__(256)
transpose_kernel(const float* __restrict__ coords)   // [NM, NA, 3] AoS
{
    int t = blockIdx.x * blockDim.x + threadIdx.x;   // over NM*NA*3 floats
    if (t < NM * NA * 3) {
        float v = coords[t];                          // coalesced read
        int atom = t / 3;
        int c    = t - 3 * atom;
        g_soa[c][atom] = v;
    }
}

__device__ __forceinline__ int cumrow(int i) {
    return i * (NA - 1) - ((i * (i - 1)) >> 1);
}

struct Quad { float iv[4], jv[4], mk[4]; };

__device__ __forceinline__ Quad make_quad(unsigned p,
                                          const float* __restrict__ xs,
                                          const float* __restrict__ ys,
                                          const float* __restrict__ zs,
                                          float off) {
    // fp32 triangular inversion (operands < 2^24, exact), exact int correction
    float disc = (float)(16769025u - 8u * p);           // 4095^2 - 8p
    int i = (int)((4095.0f - sqrtf(disc)) * 0.5f);
    if (i < 0) i = 0;
    if (i > NA - 2) i = NA - 2;
    while (cumrow(i + 1) <= (int)p) ++i;
    while (cumrow(i) > (int)p) --i;
    int j = (int)p - cumrow(i) + i + 1;

    const float c2 = 5.2f * 5.2f;
    Quad q;
    float cix = 0.f, ciy = 0.f, ciz = 0.f;
    int cached_i = -1;
    int ii = i, jj = j;
    #pragma unroll
    for (int k = 0; k < 4; ++k) {
        q.iv[k] = (float)ii + off;
        q.jv[k] = (float)jj + off;
        if (ii != cached_i) {
            cix = xs[ii]; ciy = ys[ii]; ciz = zs[ii];
            cached_i = ii;
        }
        float dx = __fsub_rn(cix, xs[jj]);
        float dy = __fsub_rn(ciy, ys[jj]);
        float dz = __fsub_rn(ciz, zs[jj]);
        // same association order as jnp.sum axis -1: (x+y)+z, no fma
        float d2 = __fadd_rn(__fadd_rn(__fmul_rn(dx, dx), __fmul_rn(dy, dy)),
                             __fmul_rn(dz, dz));
        q.mk[k] = (d2 <= c2) ? 1.0f : 0.0f;
        ++jj;
        if (jj >= NA) { ++ii; jj = ii + 1; }
    }
    return q;
}

__global__ void __launch_bounds__(256)
fullpair_kernel(float* __restrict__ out)
{
    const unsigned bid = blockIdx.x;

    // ---- suffix blocks: coalesced zero-fill of shift_values region ----
    if (bid >= (unsigned)(NM * PAIR_BLOCKS)) {
        unsigned q = (bid - NM * PAIR_BLOCKS) * THREADS + threadIdx.x;
        if (q < ZERO_F4)
            __stcs((float4*)(out + 2u * MP) + q, make_float4(0.f, 0.f, 0.f, 0.f));
        return;
    }

    // ---- pair blocks: warp owns 256 consecutive pairs; lane l does quads at
    //      base+4l and base+128+4l (both stores warp-contiguous) ----
    const int m  = bid >> 10;             // / PAIR_BLOCKS (=1024)
    const int pb = bid & 1023;
    const unsigned t = (unsigned)pb * THREADS + threadIdx.x;
    if (t >= PAIR_T) return;
    const unsigned warp = t >> 5, lane = t & 31;
    const unsigned p0 = warp * 256u + lane * 4u;   // first quad
    const unsigned p1 = p0 + 128u;                 // second quad

    const float off = (float)(m * NA);
    const float* __restrict__ xs = &g_soa[0][m * NA];
    const float* __restrict__ ys = &g_soa[1][m * NA];
    const float* __restrict__ zs = &g_soa[2][m * NA];

    const unsigned base_i = (unsigned)m * PP;            // index row 0
    const unsigned base_j = base_i + MP;                 // index row 1
    const unsigned base_k = base_i + 5u * MP;            // mask

    Quad q0 = make_quad(p0, xs, ys, zs, off);
    Quad q1 = make_quad(p1, xs, ys, zs, off);

    __stcs((float4*)(out + base_i + p0), make_float4(q0.iv[0], q0.iv[1], q0.iv[2], q0.iv[3]));
    __stcs((float4*)(out + base_j + p0), make_float4(q0.jv[0], q0.jv[1], q0.jv[2], q0.jv[3]));
    __stcs((float4*)(out + base_k + p0), make_float4(q0.mk[0], q0.mk[1], q0.mk[2], q0.mk[3]));
    __stcs((float4*)(out + base_i + p1), make_float4(q1.iv[0], q1.iv[1], q1.iv[2], q1.iv[3]));
    __stcs((float4*)(out + base_j + p1), make_float4(q1.jv[0], q1.jv[1], q1.jv[2], q1.jv[3]));
    __stcs((float4*)(out + base_k + p1), make_float4(q1.mk[0], q1.mk[1], q1.mk[2], q1.mk[3]));
}

extern "C" void kernel_launch(void* const* d_in, const int* in_sizes, int n_in,
                              void* d_out, int out_size) {
    // inputs per metadata order: species(int32), coordinates(f32), cell(f32), pbc(bool)
    const float* coords = (const float*)d_in[1];
    float* out = (float*)d_out;

    transpose_kernel<<<(NM * NA * 3 + THREADS - 1) / THREADS, THREADS>>>(coords);
    fullpair_kernel<<<NM * PAIR_BLOCKS + ZERO_BLOCKS, THREADS>>>(out);
}

// round 8
// speedup vs baseline: 1.0133x; 1.0133x over previous
#include <cuda_runtime.h>

// FullPairwise (non-PBC): output layout (float32), MP = M*P:
//   [0      , 2*MP) : atom_index12   out[r*MP + m*P + p] = (r? j : i) + m*N
//   [2*MP   , 5*MP) : shift_values   zeros (flat region, filled coalesced)
//   [5*MP   , 6*MP) : mask           1.0f if d2 <= 5.2^2 else 0.0f
// Total = 6*MP floats = 201 MB -> all offsets fit in uint32.
// This kernel is write-bandwidth bound: 201 MB / ~5.4 TB/s effective HBM
// write rate ~= 37 us. Structure: coalesced STG.128 everywhere, __stcs
// (evict-first) since output is never re-read.
static constexpr int      NA = 2048;
static constexpr int      NM = 4;
static constexpr unsigned PP = (unsigned)NA * (NA - 1) / 2;   // 2,096,128 (div by 256)
static constexpr unsigned MP = (unsigned)NM * PP;             // 8,384,512

static constexpr int      THREADS      = 256;
static constexpr unsigned PAIR_T       = PP / 8;                                  // 262,016
static constexpr int      PAIR_BLOCKS  = (int)((PAIR_T + THREADS - 1) / THREADS); // 1024
static constexpr unsigned ZERO_F4      = 3 * MP / 4;                              // 6,288,384
// 4 float4 per thread, each k-step a contiguous 256-f4 span -> 1024 f4/block
static constexpr int      ZERO_BLOCKS  = (int)((ZERO_F4 + 1023) / 1024);          // 6141

__device__ __forceinline__ int cumrow(int i) {
    return i * (NA - 1) - ((i * (i - 1)) >> 1);
}

struct Quad { float iv[4], jv[4], mk[4]; };

__device__ __forceinline__ Quad make_quad(unsigned p, const float* __restrict__ cm,
                                          float off) {
    // fp32 triangular inversion (operands < 2^24, exact), exact int correction
    float disc = (float)(16769025u - 8u * p);           // 4095^2 - 8p
    int i = (int)((4095.0f - sqrtf(disc)) * 0.5f);
    if (i < 0) i = 0;
    if (i > NA - 2) i = NA - 2;
    while (cumrow(i + 1) <= (int)p) ++i;
    while (cumrow(i) > (int)p) --i;
    int j = (int)p - cumrow(i) + i + 1;

    const float c2 = 5.2f * 5.2f;
    Quad q;
    float cix = 0.f, ciy = 0.f, ciz = 0.f;
    int cached_i = -1;
    int ii = i, jj = j;
    #pragma unroll
    for (int k = 0; k < 4; ++k) {
        q.iv[k] = (float)ii + off;
        q.jv[k] = (float)jj + off;
        if (ii != cached_i) {
            const float* ci = cm + ii * 3;
            cix = ci[0]; ciy = ci[1]; ciz = ci[2];
            cached_i = ii;
        }
        const float* cj = cm + jj * 3;
        float dx = __fsub_rn(cix, cj[0]);
        float dy = __fsub_rn(ciy, cj[1]);
        float dz = __fsub_rn(ciz, cj[2]);
        // same association order as jnp.sum axis -1: (x+y)+z, no fma
        float d2 = __fadd_rn(__fadd_rn(__fmul_rn(dx, dx), __fmul_rn(dy, dy)),
                             __fmul_rn(dz, dz));
        q.mk[k] = (d2 <= c2) ? 1.0f : 0.0f;
        ++jj;
        if (jj >= NA) { ++ii; jj = ii + 1; }
    }
    return q;
}

__global__ void __launch_bounds__(256)
fullpair_kernel(const float* __restrict__ coords,   // [NM, NA, 3] AoS
                float* __restrict__ out)
{
    const unsigned bid = blockIdx.x;

    // ---- suffix blocks: coalesced zero-fill of shift_values region ----
    if (bid >= (unsigned)(NM * PAIR_BLOCKS)) {
        const unsigned zb = bid - NM * PAIR_BLOCKS;
        float4* base = (float4*)(out + 2u * MP) + zb * 1024u;
        const float4 z = make_float4(0.f, 0.f, 0.f, 0.f);
        #pragma unroll
        for (int k = 0; k < 4; ++k) {
            unsigned idx = (unsigned)k * THREADS + threadIdx.x;  // warp-contiguous span
            if (zb * 1024u + idx < ZERO_F4)
                __stcs(base + idx, z);
        }
        return;
    }

    // ---- pair blocks: warp owns 256 consecutive pairs; lane l does quads at
    //      base+4l and base+128+4l (all stores warp-contiguous 512B spans) ----
    const int m  = bid >> 10;             // / PAIR_BLOCKS (=1024)
    const int pb = bid & 1023;
    const unsigned t = (unsigned)pb * THREADS + threadIdx.x;
    if (t >= PAIR_T) return;
    const unsigned warp = t >> 5, lane = t & 31;
    const unsigned p0 = warp * 256u + lane * 4u;   // first quad
    const unsigned p1 = p0 + 128u;                 // second quad

    const float off = (float)(m * NA);
    const float* __restrict__ cm = coords + (unsigned)m * (NA * 3);

    const unsigned base_i = (unsigned)m * PP;            // index row 0
    const unsigned base_j = base_i + MP;                 // index row 1
    const unsigned base_k = base_i + 5u * MP;            // mask

    Quad q0 = make_quad(p0, cm, off);
    Quad q1 = make_quad(p1, cm, off);

    __stcs((float4*)(out + base_i + p0), make_float4(q0.iv[0], q0.iv[1], q0.iv[2], q0.iv[3]));
    __stcs((float4*)(out + base_j + p0), make_float4(q0.jv[0], q0.jv[1], q0.jv[2], q0.jv[3]));
    __stcs((float4*)(out + base_k + p0), make_float4(q0.mk[0], q0.mk[1], q0.mk[2], q0.mk[3]));
    __stcs((float4*)(out + base_i + p1), make_float4(q1.iv[0], q1.iv[1], q1.iv[2], q1.iv[3]));
    __stcs((float4*)(out + base_j + p1), make_float4(q1.jv[0], q1.jv[1], q1.jv[2], q1.jv[3]));
    __stcs((float4*)(out + base_k + p1), make_float4(q1.mk[0], q1.mk[1], q1.mk[2], q1.mk[3]));
}

extern "C" void kernel_launch(void* const* d_in, const int* in_sizes, int n_in,
                              void* d_out, int out_size) {
    // inputs per metadata order: species(int32), coordinates(f32), cell(f32), pbc(bool)
    const float* coords = (const float*)d_in[1];
    float* out = (float*)d_out;

    fullpair_kernel<<<NM * PAIR_BLOCKS + ZERO_BLOCKS, THREADS>>>(coords, out);
}

// round 11
// speedup vs baseline: 1.1860x; 1.1704x over previous
#include <cuda_runtime.h>

// FullPairwise (non-PBC): output layout (float32), MP = M*P:
//   [0      , 2*MP) : atom_index12   out[r*MP + m*P + p] = (r? j : i) + m*N
//   [2*MP   , 5*MP) : shift_values   zeros
//   [5*MP   , 6*MP) : mask           1.0f if d2 <= 5.2^2 else 0.0f
// Total = 6*MP floats = 201 MB -> all offsets fit in uint32.
// Fused design: every thread handles 8 pairs (2 quads) of one molecule AND
// 6 float4 of the zero region -> uniform grid of 4096 blocks, 12 independent
// STG.128 per thread, all warp-contiguous.
static constexpr int      NA = 2048;
static constexpr int      NM = 4;
static constexpr unsigned PP = (unsigned)NA * (NA - 1) / 2;   // 2,096,128 (div by 2048)
static constexpr unsigned MP = (unsigned)NM * PP;             // 8,384,512

static constexpr int      THREADS     = 256;
static constexpr unsigned PAIR_T      = PP / 8;                // 262,016 per molecule
static constexpr int      PAIR_BLOCKS = (int)((PAIR_T + THREADS - 1) / THREADS);  // 1024
static constexpr unsigned TOTAL_T     = (unsigned)NM * PAIR_BLOCKS * THREADS;     // 1,048,576
static constexpr unsigned ZERO_F4     = 3 * MP / 4;            // 6,288,384 float4
// ZERO_F4 / TOTAL_T = 5.997 -> 6 per thread with guard.

__device__ __forceinline__ int cumrow(int i) {
    return i * (NA - 1) - ((i * (i - 1)) >> 1);
}

struct Quad { float iv[4], jv[4], mk[4]; };

__device__ __forceinline__ Quad make_quad(unsigned p, const float* __restrict__ cm,
                                          float off) {
    // fp32 triangular inversion (operands < 2^24, exact), exact int correction
    float disc = (float)(16769025u - 8u * p);           // 4095^2 - 8p
    int i = (int)((4095.0f - sqrtf(disc)) * 0.5f);
    if (i < 0) i = 0;
    if (i > NA - 2) i = NA - 2;
    while (cumrow(i + 1) <= (int)p) ++i;
    while (cumrow(i) > (int)p) --i;
    int j = (int)p - cumrow(i) + i + 1;

    const float c2 = 5.2f * 5.2f;
    Quad q;
    float cix = 0.f, ciy = 0.f, ciz = 0.f;
    int cached_i = -1;
    int ii = i, jj = j;
    #pragma unroll
    for (int k = 0; k < 4; ++k) {
        q.iv[k] = (float)ii + off;
        q.jv[k] = (float)jj + off;
        if (ii != cached_i) {
            const float* ci = cm + ii * 3;
            cix = ci[0]; ciy = ci[1]; ciz = ci[2];
            cached_i = ii;
        }
        const float* cj = cm + jj * 3;
        float dx = __fsub_rn(cix, cj[0]);
        float dy = __fsub_rn(ciy, cj[1]);
        float dz = __fsub_rn(ciz, cj[2]);
        // same association order as jnp.sum axis -1: (x+y)+z, no fma
        float d2 = __fadd_rn(__fadd_rn(__fmul_rn(dx, dx), __fmul_rn(dy, dy)),
                             __fmul_rn(dz, dz));
        q.mk[k] = (d2 <= c2) ? 1.0f : 0.0f;
        ++jj;
        if (jj >= NA) { ++ii; jj = ii + 1; }
    }
    return q;
}

__global__ void __launch_bounds__(256)
fullpair_kernel(const float* __restrict__ coords,   // [NM, NA, 3] AoS
                float* __restrict__ out)
{
    const unsigned bid = blockIdx.x;                  // 0 .. NM*PAIR_BLOCKS-1

    // ---- zero-fill share: block g writes zero f4 span [g*1536, g*1536+1536),
    //      thread does 6 stride-256 f4 (each warp instr = contiguous 512B) ----
    {
        const unsigned zbase = bid * (6u * THREADS);
        float4* zp = (float4*)(out + 2u * MP);
        const float4 z = make_float4(0.f, 0.f, 0.f, 0.f);
        #pragma unroll
        for (int k = 0; k < 6; ++k) {
            unsigned idx = zbase + (unsigned)k * THREADS + threadIdx.x;
            if (idx < ZERO_F4)
                __stcs(zp + idx, z);
        }
    }

    // ---- pair share: warp owns 256 consecutive pairs; lane l does quads at
    //      base+4l and base+128+4l (all stores warp-contiguous 512B spans) ----
    const int m  = bid >> 10;             // / PAIR_BLOCKS (=1024)
    const int pb = bid & 1023;
    const unsigned t = (unsigned)pb * THREADS + threadIdx.x;
    if (t >= PAIR_T) return;
    const unsigned warp = t >> 5, lane = t & 31;
    const unsigned p0 = warp * 256u + lane * 4u;   // first quad
    const unsigned p1 = p0 + 128u;                 // second quad

    const float off = (float)(m * NA);
    const float* __restrict__ cm = coords + (unsigned)m * (NA * 3);

    const unsigned base_i = (unsigned)m * PP;            // index row 0
    const unsigned base_j = base_i + MP;                 // index row 1
    const unsigned base_k = base_i + 5u * MP;            // mask

    Quad q0 = make_quad(p0, cm, off);
    Quad q1 = make_quad(p1, cm, off);

    __stcs((float4*)(out + base_i + p0), make_float4(q0.iv[0], q0.iv[1], q0.iv[2], q0.iv[3]));
    __stcs((float4*)(out + base_j + p0), make_float4(q0.jv[0], q0.jv[1], q0.jv[2], q0.jv[3]));
    __stcs((float4*)(out + base_k + p0), make_float4(q0.mk[0], q0.mk[1], q0.mk[2], q0.mk[3]));
    __stcs((float4*)(out + base_i + p1), make_float4(q1.iv[0], q1.iv[1], q1.iv[2], q1.iv[3]));
    __stcs((float4*)(out + base_j + p1), make_float4(q1.jv[0], q1.jv[1], q1.jv[2], q1.jv[3]));
    __stcs((float4*)(out + base_k + p1), make_float4(q1.mk[0], q1.mk[1], q1.mk[2], q1.mk[3]));
}

extern "C" void kernel_launch(void* const* d_in, const int* in_sizes, int n_in,
                              void* d_out, int out_size) {
    // inputs per metadata order: species(int32), coordinates(f32), cell(f32), pbc(bool)
    const float* coords = (const float*)d_in[1];
    float* out = (float*)d_out;

    fullpair_kernel<<<NM * PAIR_BLOCKS, THREADS>>>(coords, out);
}